// round 16
// baseline (speedup 1.0000x reference)
#include <cuda_runtime.h>
#include <stdint.h>
#include <math.h>

// ---------------------------------------------------------------- constants
constexpr int CB = 32, CS = 512, CD = 512;
constexpr int CSP = CS + 4;
constexpr int CIN = 3 * CD;          // 1536
constexpr int CM  = CB * CS;         // 16384
constexpr int NOUT = CM * 2 * CD;
constexpr float QF = 16256.f;        // 127*128

// ------------------------------------------------- device scratch (no alloc)
__device__ int8_t g_aH[(size_t)CB * CSP * CD];      // quantized padded input hi
__device__ int8_t g_aL[(size_t)CB * CSP * CD];      // lo
__device__ int8_t g_wpH[(size_t)2 * CD * CIN];      // proj W hi
__device__ int8_t g_wpL[(size_t)2 * CD * CIN];
__device__ int8_t g_whH[(size_t)2 * 2 * 1024 * CD]; // hw W hi
__device__ int8_t g_whL[(size_t)2 * 2 * 1024 * CD];
__device__ int8_t g_xH[(size_t)2 * CM * CD];        // quantized activations
__device__ int8_t g_xL[(size_t)2 * CM * CD];
__device__ float  g_f0[(size_t)2 * CM * CD];        // fp32 activations (proj out)
__device__ float  g_f1[(size_t)2 * CM * CD];        // fp32 activations (hw0 out)
__device__ float  g_swp[1024];                      // proj W row scales
__device__ float  g_swh[4096];                      // hw W row scales
__device__ float  g_amaxv[4];                       // tensor amax: in, proj, hw0

// SMEM: BK=128 chunk. stage = Ahi(16K)|Alo(16K)|Bhi(8K)|Blo(8K) = 48K, 2 stages
constexpr uint32_t A_TERM = 128 * 128;    // 16384
constexpr uint32_t B_TERM = 64 * 128;     // 8192
constexpr uint32_t STAGE  = 2 * A_TERM + 2 * B_TERM;   // 49152
constexpr int      NSTG   = 2;
constexpr uint32_t MBOFF  = NSTG * STAGE;              // 98304
constexpr uint32_t SMEM_SZ = MBOFF + 64;               // 98368 (2 CTAs/SM)

// swizzled byte offset of 16B slot s (0..7) in 128B row r (conflict-free)
__device__ __forceinline__ uint32_t soff(uint32_t r, uint32_t s) {
    return (r << 7) + (((s ^ (r & 7)) & 7) << 4);
}

// ---------------------------------------------------------------- PTX utils
__device__ __forceinline__ uint32_t s2u(const void* p) {
    return (uint32_t)__cvta_generic_to_shared(p);
}
__device__ __forceinline__ void cpa16(uint32_t dst, const void* src) {
    asm volatile("cp.async.cg.shared.global [%0], [%1], 16;" :: "r"(dst), "l"(src));
}
__device__ __forceinline__ void mbar_init(uint32_t a, uint32_t cnt) {
    asm volatile("mbarrier.init.shared.b64 [%0], %1;" :: "r"(a), "r"(cnt) : "memory");
}
__device__ __forceinline__ void mbar_arrive(uint32_t a) {
    asm volatile("mbarrier.arrive.shared.b64 _, [%0];" :: "r"(a) : "memory");
}
__device__ __forceinline__ void cpasync_arrive(uint32_t a) {
    // .noinc: arrive-on-completion WITHOUT bumping expected count (256 = init).
    asm volatile("cp.async.mbarrier.arrive.noinc.shared::cta.b64 [%0];" :: "r"(a) : "memory");
}
__device__ __forceinline__ void mbar_wait(uint32_t a, uint32_t parity) {
    asm volatile(
        "{\n\t.reg .pred P;\n\t"
        "WL%=:\n\t"
        "mbarrier.try_wait.parity.acquire.cta.shared::cta.b64 P, [%0], %1, 0x989680;\n\t"
        "@P bra.uni WD%=;\n\t"
        "bra.uni WL%=;\n\t"
        "WD%=:\n\t}"
        :: "r"(a), "r"(parity) : "memory");
}
__device__ __forceinline__ void ldsm4(uint32_t& r0, uint32_t& r1, uint32_t& r2,
                                      uint32_t& r3, uint32_t addr) {
    asm volatile("ldmatrix.sync.aligned.m8n8.x4.shared.b16 {%0,%1,%2,%3}, [%4];"
                 : "=r"(r0), "=r"(r1), "=r"(r2), "=r"(r3) : "r"(addr));
}
__device__ __forceinline__ void mma_s8(int* d, const uint32_t* a, const uint32_t* b) {
    asm volatile(
        "mma.sync.aligned.m16n8k32.row.col.s32.s8.s8.s32 "
        "{%0,%1,%2,%3},{%4,%5,%6,%7},{%8,%9},{%0,%1,%2,%3};"
        : "+r"(d[0]), "+r"(d[1]), "+r"(d[2]), "+r"(d[3])
        : "r"(a[0]), "r"(a[1]), "r"(a[2]), "r"(a[3]), "r"(b[0]), "r"(b[1]));
}
// fixed-point 2-limb quantization: x ~= s*(hi*128+lo), s = amax/16256
__device__ __forceinline__ void quant2(float x, float inv_s, int8_t& h, int8_t& l) {
    int q  = __float2int_rn(x * inv_s);
    int hi = (q + 64) >> 7;
    h = (int8_t)hi;
    l = (int8_t)(q - (hi << 7));
}
__device__ __forceinline__ void amax_atomic(float v, int idx) {
    atomicMax((int*)g_amaxv + idx, __float_as_int(v));
}
__device__ __forceinline__ float warp_max(float v) {
    #pragma unroll
    for (int o = 16; o; o >>= 1) v = fmaxf(v, __shfl_xor_sync(0xffffffffu, v, o));
    return v;
}

// ---------------------------------------------------------------- aux kernels
__global__ void zero_amax() { if (threadIdx.x < 4) g_amaxv[threadIdx.x] = 0.f; }

__global__ void amax_in(const float* __restrict__ inp, const float* __restrict__ lp,
                        const float* __restrict__ rp) {
    int idx = blockIdx.x * blockDim.x + threadIdx.x;
    const int NI = CB * CS * CD / 4;
    float4 v;
    if (idx < NI) v = ((const float4*)inp)[idx];
    else if (idx < NI + 256) v = ((const float4*)lp)[idx - NI];
    else if (idx < NI + 512) v = ((const float4*)rp)[idx - NI - 256];
    else return;
    float m = fmaxf(fmaxf(fabsf(v.x), fabsf(v.y)), fmaxf(fabsf(v.z), fabsf(v.w)));
    m = warp_max(m);
    if ((threadIdx.x & 31) == 0) amax_atomic(m, 0);
}

// merged: blocks [0, PADQ_BLKS) pad+quantize input; rest weight-quant rows.
constexpr int PADQ_BLKS = CB * CSP * (CD / 4) / 128;   // 16512
__global__ void prep_quant(const float* __restrict__ inp, const float* __restrict__ lp,
                           const float* __restrict__ rp,
                           const float* __restrict__ lW, const float* __restrict__ rW,
                           const float* __restrict__ lhw, const float* __restrict__ rhw) {
    if (blockIdx.x < PADQ_BLKS) {
        int idx = blockIdx.x * 128 + threadIdx.x;           // float4 units
        const int per_b = CSP * (CD / 4);
        int b = idx / per_b, rem = idx - b * per_b;
        int row = rem >> 7, d4 = rem & 127;
        float4 v;
        if (row < 2)             v = ((const float4*)lp)[row * 128 + d4];
        else if (row >= CSP - 2) v = ((const float4*)rp)[(row - (CSP - 2)) * 128 + d4];
        else v = ((const float4*)inp)[((size_t)b * CS + (row - 2)) * 128 + d4];
        float inv_s = QF / fmaxf(g_amaxv[0], 1e-30f);
        char4 h, l;
        quant2(v.x, inv_s, (int8_t&)h.x, (int8_t&)l.x);
        quant2(v.y, inv_s, (int8_t&)h.y, (int8_t&)l.y);
        quant2(v.z, inv_s, (int8_t&)h.z, (int8_t&)l.z);
        quant2(v.w, inv_s, (int8_t&)h.w, (int8_t&)l.w);
        ((char4*)g_aH)[idx] = h;
        ((char4*)g_aL)[idx] = l;
        return;
    }
    __shared__ float red[128];
    int blk = blockIdx.x - PADQ_BLKS, t = threadIdx.x;
    const float* src; int K; int8_t *dh, *dl; float* sc;
    if (blk < 1024) {
        int r = blk; K = CIN;
        src = (r < 512) ? (lW + (size_t)r * CIN) : (rW + (size_t)(r - 512) * CIN);
        dh = g_wpH + (size_t)blk * CIN; dl = g_wpL + (size_t)blk * CIN; sc = g_swp + blk;
    } else {
        int m = blk - 1024; K = CD;
        int side = m >> 11, layer = (m >> 10) & 1, e = m & 1023;
        src = (side ? rhw : lhw) + ((size_t)layer * 1024 + e) * CD;
        dh = g_whH + (size_t)m * CD; dl = g_whL + (size_t)m * CD; sc = g_swh + m;
    }
    float mx = 0.f;
    for (int i = t; i < K; i += 128) mx = fmaxf(mx, fabsf(src[i]));
    red[t] = mx; __syncthreads();
    for (int o = 64; o; o >>= 1) { if (t < o) red[t] = fmaxf(red[t], red[t + o]); __syncthreads(); }
    float amax = fmaxf(red[0], 1e-30f);
    if (t == 0) *sc = amax * (1.f / QF);
    float inv_s = QF / amax;
    for (int i = t; i < K; i += 128) {
        int8_t h, l; quant2(src[i], inv_s, h, l);
        dh[i] = h; dl[i] = l;
    }
}

// quantize fp32 activation tensor with global scale g_amaxv[aidx]
__global__ void quant_act(const float* __restrict__ fin, int aidx) {
    int idx = blockIdx.x * blockDim.x + threadIdx.x;       // float4 units
    if (idx >= 2 * CM * CD / 4) return;
    float4 v = ((const float4*)fin)[idx];
    float inv_s = QF / fmaxf(g_amaxv[aidx], 1e-30f);
    char4 h, l;
    quant2(v.x, inv_s, (int8_t&)h.x, (int8_t&)l.x);
    quant2(v.y, inv_s, (int8_t&)h.y, (int8_t&)l.y);
    quant2(v.z, inv_s, (int8_t&)h.z, (int8_t&)l.z);
    quant2(v.w, inv_s, (int8_t&)h.w, (int8_t&)l.w);
    ((char4*)g_xH)[idx] = h;
    ((char4*)g_xL)[idx] = l;
}

// ------------------------------------------------- int8 GEMM micro-kernel
__device__ __forceinline__ void cchunk_i8(uint32_t base, int lane,
                                          int mbase, int nbase, uint32_t emptyb,
                                          int accH[2][4][4], int accX[2][4][4]) {
    uint32_t aHs = base, aLs = base + A_TERM;
    uint32_t bHs = base + 2 * A_TERM, bLs = bHs + B_TERM;
    uint32_t arow = (uint32_t)(mbase + (lane & 7) + ((lane >> 3) & 1) * 8);
    uint32_t brow = (uint32_t)(nbase + ((lane >> 4) & 1) * 8 + (lane & 7));
    #pragma unroll
    for (int ks = 0; ks < 4; ++ks) {
        uint32_t ahf[2][4], alf[2][4], bhf[4][2], blf[4][2];
        uint32_t aslot = (uint32_t)(2 * ks + (lane >> 4));
        uint32_t bslot = (uint32_t)(2 * ks + ((lane >> 3) & 1));
        #pragma unroll
        for (int mt = 0; mt < 2; ++mt)
            ldsm4(ahf[mt][0], ahf[mt][1], ahf[mt][2], ahf[mt][3],
                  aHs + soff(arow + mt * 16, aslot));
        #pragma unroll
        for (int jp = 0; jp < 2; ++jp)
            ldsm4(bhf[jp*2][0], bhf[jp*2][1], bhf[jp*2+1][0], bhf[jp*2+1][1],
                  bHs + soff(brow + jp * 16, bslot));
        #pragma unroll
        for (int i = 0; i < 2; ++i)
            #pragma unroll
            for (int j = 0; j < 4; ++j)
                mma_s8(accH[i][j], ahf[i], bhf[j]);
        #pragma unroll
        for (int mt = 0; mt < 2; ++mt)
            ldsm4(alf[mt][0], alf[mt][1], alf[mt][2], alf[mt][3],
                  aLs + soff(arow + mt * 16, aslot));
        #pragma unroll
        for (int jp = 0; jp < 2; ++jp)
            ldsm4(blf[jp*2][0], blf[jp*2][1], blf[jp*2+1][0], blf[jp*2+1][1],
                  bLs + soff(brow + jp * 16, bslot));
        if (ks == 3 && lane == 0) mbar_arrive(emptyb);   // stage fully read
        #pragma unroll
        for (int i = 0; i < 2; ++i)
            #pragma unroll
            for (int j = 0; j < 4; ++j)
                mma_s8(accX[i][j], ahf[i], blf[j]);
        #pragma unroll
        for (int i = 0; i < 2; ++i)
            #pragma unroll
            for (int j = 0; j < 4; ++j)
                mma_s8(accX[i][j], alf[i], bhf[j]);
    }
}

#define FULLB(s)  (sb + MBOFF + (uint32_t)(s) * 16)
#define EMPTYB(s) (sb + MBOFF + (uint32_t)(s) * 16 + 8)

// 2-stage pipeline, prefetch distance 1, fully unrolled (constant parities).
#define GEMM_LOOP(C)                                                          \
    do {                                                                      \
        issue_chunk(0, 0);                                                    \
        _Pragma("unroll")                                                     \
        for (int c = 0; c < (C); ++c) {                                       \
            const int k = c + 1;                                              \
            if (k < (C)) {                                                    \
                if (k >= 2) mbar_wait(EMPTYB(k & 1), (uint32_t)(((k >> 1) - 1) & 1)); \
                issue_chunk(k, k & 1);                                        \
            }                                                                 \
            mbar_wait(FULLB(c & 1), (uint32_t)((c >> 1) & 1));                \
            cchunk_i8(sb + (uint32_t)(c & 1) * STAGE, lane, mbase, nbase,     \
                      EMPTYB(c & 1), accH, accX);                             \
        }                                                                     \
    } while (0)

// ---------------------------------------------------------------- proj GEMM
// block: 128 tokens x 64 h; K=1536; direct fragment->global epilogue
__global__ __launch_bounds__(256, 2) void proj_i8(const float* __restrict__ lb,
                                                  const float* __restrict__ rb) {
    extern __shared__ char smem[];
    uint32_t sb = s2u(smem);
    const int tid = threadIdx.x, lane = tid & 31, wid = tid >> 5;
    const int mbase = (wid & 3) * 32, nbase = (wid >> 2) * 32;
    const int side = blockIdx.z, h0 = blockIdx.y * 64, token0 = blockIdx.x * 128;
    const int b = token0 >> 9, t0 = token0 & 511;

    const size_t abase = (size_t)(b * CSP + t0 + side * 2) * CD;
    const size_t wbase = (size_t)(side * 512 + h0) * CIN;

    if (tid == 0) {
        #pragma unroll
        for (int s = 0; s < NSTG; ++s) {
            mbar_init(FULLB(s), 256);
            mbar_init(EMPTYB(s), 8);
        }
    }
    __syncthreads();

    int accH[2][4][4] = {}, accX[2][4][4] = {};

    auto issue_chunk = [&](int c, int s) {
        uint32_t base = sb + (uint32_t)s * STAGE;
        int kb = c * 128;
        #pragma unroll
        for (int t = 0; t < 4; ++t) {
            int ci = tid + t * 256;
            uint32_t row = (uint32_t)(ci >> 3), slot = (uint32_t)(ci & 7);
            uint32_t so = soff(row, slot);
            size_t ga = abase + (size_t)row * CD + kb + slot * 16;
            cpa16(base + so,          g_aH + ga);
            cpa16(base + A_TERM + so, g_aL + ga);
        }
        #pragma unroll
        for (int t = 0; t < 2; ++t) {
            int ci = tid + t * 256;
            uint32_t row = (uint32_t)(ci >> 3), slot = (uint32_t)(ci & 7);
            uint32_t so = soff(row, slot);
            size_t gw = wbase + (size_t)row * CIN + kb + slot * 16;
            cpa16(base + 2 * A_TERM + so,          g_wpH + gw);
            cpa16(base + 2 * A_TERM + B_TERM + so, g_wpL + gw);
        }
        cpasync_arrive(FULLB(s));
    };

    GEMM_LOOP(CIN / 128);   // 12 chunks

    // direct epilogue: dequant + bias + relu, float2 stores (32B aligned)
    const float* bias = side ? rb : lb;
    const float sA = g_amaxv[0] * (1.f / QF);
    float tmax = 0.f;
    #pragma unroll
    for (int i = 0; i < 2; ++i)
        #pragma unroll
        for (int j = 0; j < 4; ++j) {
            int r = mbase + i * 16 + (lane >> 2);
            int c = nbase + j * 8 + (lane & 3) * 2;
            float s0 = sA * g_swp[side * 512 + h0 + c];
            float s1 = sA * g_swp[side * 512 + h0 + c + 1];
            #pragma unroll
            for (int half = 0; half < 2; ++half) {
                int rr = r + half * 8;
                float v0 = fmaxf(s0 * ((float)accH[i][j][half*2]   * 16384.f +
                                       (float)accX[i][j][half*2]   * 128.f) + bias[h0 + c], 0.f);
                float v1 = fmaxf(s1 * ((float)accH[i][j][half*2+1] * 16384.f +
                                       (float)accX[i][j][half*2+1] * 128.f) + bias[h0 + c + 1], 0.f);
                tmax = fmaxf(tmax, fmaxf(v0, v1));
                *(float2*)(g_f0 + ((size_t)side * CM + token0 + rr) * CD + h0 + c) =
                    make_float2(v0, v1);
            }
        }
    tmax = warp_max(tmax);
    if (lane == 0) amax_atomic(tmax, 1);
}

// ---------------------------------------------------------------- highway GEMM
// block: 128 tokens x 64 B-rows (32 nonlin [n-warps 0], 32 gate [n-warps 1])
__global__ __launch_bounds__(256, 2) void hw_i8(const float* __restrict__ fin,
                                                float* __restrict__ fout,
                                                const float* __restrict__ lhwb,
                                                const float* __restrict__ rhwb,
                                                int layer, int aidx,
                                                float* __restrict__ out, int dup) {
    extern __shared__ char smem[];
    uint32_t sb = s2u(smem);
    const int tid = threadIdx.x, lane = tid & 31, wid = tid >> 5;
    const int mbase = (wid & 3) * 32, nbase = (wid >> 2) * 32;
    const int side = blockIdx.z, h0 = blockIdx.y * 32, token0 = blockIdx.x * 128;

    const size_t abase = ((size_t)side * CM + token0) * CD;
    const size_t wrow0 = (size_t)((side * 2 + layer) * 1024);

    if (tid == 0) {
        #pragma unroll
        for (int s = 0; s < NSTG; ++s) {
            mbar_init(FULLB(s), 256);
            mbar_init(EMPTYB(s), 8);
        }
    }
    __syncthreads();

    int accH[2][4][4] = {}, accX[2][4][4] = {};

    auto issue_chunk = [&](int c, int s) {
        uint32_t base = sb + (uint32_t)s * STAGE;
        int kb = c * 128;
        #pragma unroll
        for (int t = 0; t < 4; ++t) {
            int ci = tid + t * 256;
            uint32_t row = (uint32_t)(ci >> 3), slot = (uint32_t)(ci & 7);
            uint32_t so = soff(row, slot);
            size_t ga = abase + (size_t)row * CD + kb + slot * 16;
            cpa16(base + so,          g_xH + ga);
            cpa16(base + A_TERM + so, g_xL + ga);
        }
        #pragma unroll
        for (int t = 0; t < 2; ++t) {
            int ci = tid + t * 256;
            uint32_t row = (uint32_t)(ci >> 3), slot = (uint32_t)(ci & 7);
            int e = (row < 32) ? (h0 + (int)row) : (512 + h0 + (int)row - 32);
            uint32_t so = soff(row, slot);
            size_t gw = (wrow0 + e) * CD + kb + slot * 16;
            cpa16(base + 2 * A_TERM + so,          g_whH + gw);
            cpa16(base + 2 * A_TERM + B_TERM + so, g_whL + gw);
        }
        cpasync_arrive(FULLB(s));
    };

    GEMM_LOOP(CD / 128);    // 4 chunks
    __syncthreads();

    // epilogue: n=1 warps write gate pre-activation to SMEM; n=0 combine+store
    const float* bias = (side ? rhwb : lhwb) + (size_t)layer * 1024;
    const float sA = g_amaxv[aidx] * (1.f / QF);
    float* svG = (float*)smem;                  // [128][33]
    if (nbase == 32) {                          // gate warps: cols 32..63 local
        #pragma unroll
        for (int i = 0; i < 2; ++i)
            #pragma unroll
            for (int j = 0; j < 4; ++j) {
                int r = mbase + i * 16 + (lane >> 2);
                int c = j * 8 + (lane & 3) * 2;            // local gate col 0..31
                float s0 = sA * g_swh[wrow0 + 512 + h0 + c];
                float s1 = sA * g_swh[wrow0 + 512 + h0 + c + 1];
                #pragma unroll
                for (int half = 0; half < 2; ++half) {
                    int rr = r + half * 8;
                    svG[rr * 33 + c]     = s0 * ((float)accH[i][j][half*2]   * 16384.f +
                                                 (float)accX[i][j][half*2]   * 128.f);
                    svG[rr * 33 + c + 1] = s1 * ((float)accH[i][j][half*2+1] * 16384.f +
                                                 (float)accX[i][j][half*2+1] * 128.f);
                }
            }
    }
    __syncthreads();
    if (nbase == 0) {                           // nonlin warps: combine + store
        float tmax = 0.f;
        #pragma unroll
        for (int i = 0; i < 2; ++i)
            #pragma unroll
            for (int j = 0; j < 4; ++j) {
                int r = mbase + i * 16 + (lane >> 2);
                int c = j * 8 + (lane & 3) * 2;
                float s0 = sA * g_swh[wrow0 + h0 + c];
                float s1 = sA * g_swh[wrow0 + h0 + c + 1];
                #pragma unroll
                for (int half = 0; half < 2; ++half) {
                    int rr = r + half * 8;
                    int token = token0 + rr;
                    float2 xv = *(const float2*)(fin + ((size_t)side * CM + token) * CD + h0 + c);
                    float nl0 = fmaxf(s0 * ((float)accH[i][j][half*2]   * 16384.f +
                                            (float)accX[i][j][half*2]   * 128.f) + bias[h0 + c], 0.f);
                    float nl1 = fmaxf(s1 * ((float)accH[i][j][half*2+1] * 16384.f +
                                            (float)accX[i][j][half*2+1] * 128.f) + bias[h0 + c + 1], 0.f);
                    float gg0 = 1.f / (1.f + expf(-(svG[rr * 33 + c]     + bias[512 + h0 + c])));
                    float gg1 = 1.f / (1.f + expf(-(svG[rr * 33 + c + 1] + bias[512 + h0 + c + 1])));
                    float v0 = gg0 * xv.x + (1.f - gg0) * nl0;
                    float v1 = gg1 * xv.y + (1.f - gg1) * nl1;
                    tmax = fmaxf(tmax, fmaxf(fabsf(v0), fabsf(v1)));
                    if (out) {
                        size_t oo = (size_t)token * 1024 + (size_t)side * 512 + h0 + c;
                        *(float2*)(out + oo) = make_float2(v0, v1);
                        if (dup) *(float2*)(out + NOUT + oo) = make_float2(v0, v1);
                    } else {
                        *(float2*)(fout + ((size_t)side * CM + token) * CD + h0 + c) =
                            make_float2(v0, v1);
                    }
                }
            }
        if (!out) {
            tmax = warp_max(tmax);
            if (lane == 0) amax_atomic(tmax, aidx + 1);
        }
    }
}

// ---------------------------------------------------------------- launcher
extern "C" void kernel_launch(void* const* d_in, const int* in_sizes, int n_in,
                              void* d_out, int out_size) {
    const float* inputs = (const float*)d_in[0];
    const float* lpad   = (const float*)d_in[1];
    const float* rpad   = (const float*)d_in[2];
    const float* lW     = (const float*)d_in[3];
    const float* lb     = (const float*)d_in[4];
    const float* rW     = (const float*)d_in[5];
    const float* rb     = (const float*)d_in[6];
    const float* lhwW   = (const float*)d_in[7];
    const float* lhwb   = (const float*)d_in[8];
    const float* rhwW   = (const float*)d_in[9];
    const float* rhwb   = (const float*)d_in[10];
    float* out = (float*)d_out;
    int dup = (out_size >= 2 * NOUT) ? 1 : 0;

    cudaFuncSetAttribute(proj_i8, cudaFuncAttributeMaxDynamicSharedMemorySize, SMEM_SZ);
    cudaFuncSetAttribute(hw_i8,   cudaFuncAttributeMaxDynamicSharedMemorySize, SMEM_SZ);

    float *f0, *f1;
    cudaGetSymbolAddress((void**)&f0, g_f0);
    cudaGetSymbolAddress((void**)&f1, g_f1);

    zero_amax<<<1, 32>>>();
    amax_in<<<(CB * CS * CD / 4 + 512 + 255) / 256, 256>>>(inputs, lpad, rpad);
    prep_quant<<<PADQ_BLKS + 5120, 128>>>(inputs, lpad, rpad, lW, rW, lhwW, rhwW);
    proj_i8<<<dim3(CM / 128, 8, 2), 256, SMEM_SZ>>>(lb, rb);
    quant_act<<<(2 * CM * CD / 4 + 255) / 256, 256>>>(f0, 1);
    hw_i8<<<dim3(CM / 128, 16, 2), 256, SMEM_SZ>>>(f0, f1, lhwb, rhwb, 0, 1, nullptr, 0);
    quant_act<<<(2 * CM * CD / 4 + 255) / 256, 256>>>(f1, 2);
    hw_i8<<<dim3(CM / 128, 16, 2), 256, SMEM_SZ>>>(f1, nullptr, lhwb, rhwb, 1, 2, out, dup);
}

// round 17
// speedup vs baseline: 1.0814x; 1.0814x over previous
#include <cuda_runtime.h>
#include <stdint.h>
#include <math.h>

// ---------------------------------------------------------------- constants
constexpr int CB = 32, CS = 512, CD = 512;
constexpr int CSP = CS + 4;
constexpr int CIN = 3 * CD;          // 1536
constexpr int CM  = CB * CS;         // 16384
constexpr int NOUT = CM * 2 * CD;
constexpr float QF = 16256.f;        // 127*128

// ------------------------------------------------- device scratch (no alloc)
__device__ int8_t g_aH[(size_t)CB * CSP * CD];      // quantized padded input hi
__device__ int8_t g_aL[(size_t)CB * CSP * CD];      // lo
__device__ int8_t g_wpH[(size_t)2 * CD * CIN];      // proj W hi
__device__ int8_t g_wpL[(size_t)2 * CD * CIN];
__device__ int8_t g_whH[(size_t)2 * 2 * 1024 * CD]; // hw W hi
__device__ int8_t g_whL[(size_t)2 * 2 * 1024 * CD];
__device__ int8_t g_xH[(size_t)2 * CM * CD];        // quantized activations
__device__ int8_t g_xL[(size_t)2 * CM * CD];
__device__ float  g_f0[(size_t)2 * CM * CD];        // fp32 activations (proj out)
__device__ float  g_f1[(size_t)2 * CM * CD];        // fp32 activations (hw0 out)
__device__ float  g_swp[1024];                      // proj W row scales
__device__ float  g_swh[4096];                      // hw W row scales
__device__ float  g_amaxv[4];                       // tensor amax: in, proj, hw0

// SMEM: BK=128 chunk. stage = Ahi(16K)|Alo(16K)|Bhi(8K)|Blo(8K) = 48K, 2 stages
constexpr uint32_t A_TERM = 128 * 128;    // 16384
constexpr uint32_t B_TERM = 64 * 128;     // 8192
constexpr uint32_t STAGE  = 2 * A_TERM + 2 * B_TERM;   // 49152
constexpr int      NSTG   = 2;
constexpr uint32_t MBOFF  = NSTG * STAGE;              // 98304
constexpr uint32_t SMEM_SZ = MBOFF + 64;               // 98368 (2 CTAs/SM)

// swizzled byte offset of 16B slot s (0..7) in 128B row r (conflict-free)
__device__ __forceinline__ uint32_t soff(uint32_t r, uint32_t s) {
    return (r << 7) + (((s ^ (r & 7)) & 7) << 4);
}

// ---------------------------------------------------------------- PTX utils
__device__ __forceinline__ uint32_t s2u(const void* p) {
    return (uint32_t)__cvta_generic_to_shared(p);
}
__device__ __forceinline__ void cpa16(uint32_t dst, const void* src) {
    asm volatile("cp.async.cg.shared.global [%0], [%1], 16;" :: "r"(dst), "l"(src));
}
__device__ __forceinline__ void mbar_init(uint32_t a, uint32_t cnt) {
    asm volatile("mbarrier.init.shared.b64 [%0], %1;" :: "r"(a), "r"(cnt) : "memory");
}
__device__ __forceinline__ void mbar_arrive(uint32_t a) {
    asm volatile("mbarrier.arrive.shared.b64 _, [%0];" :: "r"(a) : "memory");
}
__device__ __forceinline__ void cpasync_arrive(uint32_t a) {
    // .noinc: arrive-on-completion WITHOUT bumping expected count (256 = init).
    asm volatile("cp.async.mbarrier.arrive.noinc.shared::cta.b64 [%0];" :: "r"(a) : "memory");
}
__device__ __forceinline__ void mbar_wait(uint32_t a, uint32_t parity) {
    asm volatile(
        "{\n\t.reg .pred P;\n\t"
        "WL%=:\n\t"
        "mbarrier.try_wait.parity.acquire.cta.shared::cta.b64 P, [%0], %1, 0x989680;\n\t"
        "@P bra.uni WD%=;\n\t"
        "bra.uni WL%=;\n\t"
        "WD%=:\n\t}"
        :: "r"(a), "r"(parity) : "memory");
}
__device__ __forceinline__ void ldsm4(uint32_t& r0, uint32_t& r1, uint32_t& r2,
                                      uint32_t& r3, uint32_t addr) {
    asm volatile("ldmatrix.sync.aligned.m8n8.x4.shared.b16 {%0,%1,%2,%3}, [%4];"
                 : "=r"(r0), "=r"(r1), "=r"(r2), "=r"(r3) : "r"(addr));
}
__device__ __forceinline__ void mma_s8(int* d, const uint32_t* a, const uint32_t* b) {
    asm volatile(
        "mma.sync.aligned.m16n8k32.row.col.s32.s8.s8.s32 "
        "{%0,%1,%2,%3},{%4,%5,%6,%7},{%8,%9},{%0,%1,%2,%3};"
        : "+r"(d[0]), "+r"(d[1]), "+r"(d[2]), "+r"(d[3])
        : "r"(a[0]), "r"(a[1]), "r"(a[2]), "r"(a[3]), "r"(b[0]), "r"(b[1]));
}
// fixed-point 2-limb quantization: x ~= s*(hi*128+lo), s = amax/16256
__device__ __forceinline__ void quant2(float x, float inv_s, int8_t& h, int8_t& l) {
    int q  = __float2int_rn(x * inv_s);
    int hi = (q + 64) >> 7;
    h = (int8_t)hi;
    l = (int8_t)(q - (hi << 7));
}
__device__ __forceinline__ void amax_atomic(float v, int idx) {
    atomicMax((int*)g_amaxv + idx, __float_as_int(v));
}
__device__ __forceinline__ float warp_max(float v) {
    #pragma unroll
    for (int o = 16; o; o >>= 1) v = fmaxf(v, __shfl_xor_sync(0xffffffffu, v, o));
    return v;
}

// ---------------------------------------------------------------- aux kernels
__global__ void zero_amax() { if (threadIdx.x < 4) g_amaxv[threadIdx.x] = 0.f; }

__global__ void amax_in(const float* __restrict__ inp, const float* __restrict__ lp,
                        const float* __restrict__ rp) {
    int idx = blockIdx.x * blockDim.x + threadIdx.x;
    const int NI = CB * CS * CD / 4;
    float4 v;
    if (idx < NI) v = ((const float4*)inp)[idx];
    else if (idx < NI + 256) v = ((const float4*)lp)[idx - NI];
    else if (idx < NI + 512) v = ((const float4*)rp)[idx - NI - 256];
    else return;
    float m = fmaxf(fmaxf(fabsf(v.x), fabsf(v.y)), fmaxf(fabsf(v.z), fabsf(v.w)));
    m = warp_max(m);
    if ((threadIdx.x & 31) == 0) amax_atomic(m, 0);
}

// merged: blocks [0, PADQ_BLKS) pad+quantize input; rest weight-quant rows.
constexpr int PADQ_BLKS = CB * CSP * (CD / 4) / 128;   // 16512
__global__ void prep_quant(const float* __restrict__ inp, const float* __restrict__ lp,
                           const float* __restrict__ rp,
                           const float* __restrict__ lW, const float* __restrict__ rW,
                           const float* __restrict__ lhw, const float* __restrict__ rhw) {
    if (blockIdx.x < PADQ_BLKS) {
        int idx = blockIdx.x * 128 + threadIdx.x;           // float4 units
        const int per_b = CSP * (CD / 4);
        int b = idx / per_b, rem = idx - b * per_b;
        int row = rem >> 7, d4 = rem & 127;
        float4 v;
        if (row < 2)             v = ((const float4*)lp)[row * 128 + d4];
        else if (row >= CSP - 2) v = ((const float4*)rp)[(row - (CSP - 2)) * 128 + d4];
        else v = ((const float4*)inp)[((size_t)b * CS + (row - 2)) * 128 + d4];
        float inv_s = QF / fmaxf(g_amaxv[0], 1e-30f);
        char4 h, l;
        quant2(v.x, inv_s, (int8_t&)h.x, (int8_t&)l.x);
        quant2(v.y, inv_s, (int8_t&)h.y, (int8_t&)l.y);
        quant2(v.z, inv_s, (int8_t&)h.z, (int8_t&)l.z);
        quant2(v.w, inv_s, (int8_t&)h.w, (int8_t&)l.w);
        ((char4*)g_aH)[idx] = h;
        ((char4*)g_aL)[idx] = l;
        return;
    }
    __shared__ float red[128];
    int blk = blockIdx.x - PADQ_BLKS, t = threadIdx.x;
    const float* src; int K; int8_t *dh, *dl; float* sc;
    if (blk < 1024) {
        int r = blk; K = CIN;
        src = (r < 512) ? (lW + (size_t)r * CIN) : (rW + (size_t)(r - 512) * CIN);
        dh = g_wpH + (size_t)blk * CIN; dl = g_wpL + (size_t)blk * CIN; sc = g_swp + blk;
    } else {
        int m = blk - 1024; K = CD;
        int side = m >> 11, layer = (m >> 10) & 1, e = m & 1023;
        src = (side ? rhw : lhw) + ((size_t)layer * 1024 + e) * CD;
        dh = g_whH + (size_t)m * CD; dl = g_whL + (size_t)m * CD; sc = g_swh + m;
    }
    float mx = 0.f;
    for (int i = t; i < K; i += 128) mx = fmaxf(mx, fabsf(src[i]));
    red[t] = mx; __syncthreads();
    for (int o = 64; o; o >>= 1) { if (t < o) red[t] = fmaxf(red[t], red[t + o]); __syncthreads(); }
    float amax = fmaxf(red[0], 1e-30f);
    if (t == 0) *sc = amax * (1.f / QF);
    float inv_s = QF / amax;
    for (int i = t; i < K; i += 128) {
        int8_t h, l; quant2(src[i], inv_s, h, l);
        dh[i] = h; dl[i] = l;
    }
}

// quantize fp32 activation tensor with global scale g_amaxv[aidx]
__global__ void quant_act(const float* __restrict__ fin, int aidx) {
    int idx = blockIdx.x * blockDim.x + threadIdx.x;       // float4 units
    if (idx >= 2 * CM * CD / 4) return;
    float4 v = ((const float4*)fin)[idx];
    float inv_s = QF / fmaxf(g_amaxv[aidx], 1e-30f);
    char4 h, l;
    quant2(v.x, inv_s, (int8_t&)h.x, (int8_t&)l.x);
    quant2(v.y, inv_s, (int8_t&)h.y, (int8_t&)l.y);
    quant2(v.z, inv_s, (int8_t&)h.z, (int8_t&)l.z);
    quant2(v.w, inv_s, (int8_t&)h.w, (int8_t&)l.w);
    ((char4*)g_xH)[idx] = h;
    ((char4*)g_xL)[idx] = l;
}

// ------------------------------------------------- int8 GEMM micro-kernel
__device__ __forceinline__ void cchunk_i8(uint32_t base, int lane,
                                          int mbase, int nbase, uint32_t emptyb,
                                          int accH[2][4][4], int accX[2][4][4]) {
    uint32_t aHs = base, aLs = base + A_TERM;
    uint32_t bHs = base + 2 * A_TERM, bLs = bHs + B_TERM;
    uint32_t arow = (uint32_t)(mbase + (lane & 7) + ((lane >> 3) & 1) * 8);
    uint32_t brow = (uint32_t)(nbase + ((lane >> 4) & 1) * 8 + (lane & 7));
    #pragma unroll
    for (int ks = 0; ks < 4; ++ks) {
        uint32_t ahf[2][4], alf[2][4], bhf[4][2], blf[4][2];
        uint32_t aslot = (uint32_t)(2 * ks + (lane >> 4));
        uint32_t bslot = (uint32_t)(2 * ks + ((lane >> 3) & 1));
        #pragma unroll
        for (int mt = 0; mt < 2; ++mt)
            ldsm4(ahf[mt][0], ahf[mt][1], ahf[mt][2], ahf[mt][3],
                  aHs + soff(arow + mt * 16, aslot));
        #pragma unroll
        for (int jp = 0; jp < 2; ++jp)
            ldsm4(bhf[jp*2][0], bhf[jp*2][1], bhf[jp*2+1][0], bhf[jp*2+1][1],
                  bHs + soff(brow + jp * 16, bslot));
        #pragma unroll
        for (int i = 0; i < 2; ++i)
            #pragma unroll
            for (int j = 0; j < 4; ++j)
                mma_s8(accH[i][j], ahf[i], bhf[j]);
        #pragma unroll
        for (int mt = 0; mt < 2; ++mt)
            ldsm4(alf[mt][0], alf[mt][1], alf[mt][2], alf[mt][3],
                  aLs + soff(arow + mt * 16, aslot));
        #pragma unroll
        for (int jp = 0; jp < 2; ++jp)
            ldsm4(blf[jp*2][0], blf[jp*2][1], blf[jp*2+1][0], blf[jp*2+1][1],
                  bLs + soff(brow + jp * 16, bslot));
        if (ks == 3 && lane == 0) mbar_arrive(emptyb);   // stage fully read
        #pragma unroll
        for (int i = 0; i < 2; ++i)
            #pragma unroll
            for (int j = 0; j < 4; ++j)
                mma_s8(accX[i][j], ahf[i], blf[j]);
        #pragma unroll
        for (int i = 0; i < 2; ++i)
            #pragma unroll
            for (int j = 0; j < 4; ++j)
                mma_s8(accX[i][j], alf[i], bhf[j]);
    }
}

__device__ __forceinline__ void acc2smem_i8(int* svH, int* svX, int lane,
                                            int mbase, int nbase,
                                            int accH[2][4][4], int accX[2][4][4]) {
    #pragma unroll
    for (int i = 0; i < 2; ++i)
        #pragma unroll
        for (int j = 0; j < 4; ++j) {
            int r = mbase + i * 16 + (lane >> 2);
            int c = nbase + j * 8 + (lane & 3) * 2;
            svH[r * 68 + c]           = accH[i][j][0];
            svH[r * 68 + c + 1]       = accH[i][j][1];
            svH[(r + 8) * 68 + c]     = accH[i][j][2];
            svH[(r + 8) * 68 + c + 1] = accH[i][j][3];
            svX[r * 68 + c]           = accX[i][j][0];
            svX[r * 68 + c + 1]       = accX[i][j][1];
            svX[(r + 8) * 68 + c]     = accX[i][j][2];
            svX[(r + 8) * 68 + c + 1] = accX[i][j][3];
        }
}

#define FULLB(s)  (sb + MBOFF + (uint32_t)(s) * 16)
#define EMPTYB(s) (sb + MBOFF + (uint32_t)(s) * 16 + 8)

// 2-stage pipeline, prefetch distance 1, fully unrolled (constant parities).
#define GEMM_LOOP(C)                                                          \
    do {                                                                      \
        issue_chunk(0, 0);                                                    \
        _Pragma("unroll")                                                     \
        for (int c = 0; c < (C); ++c) {                                       \
            const int k = c + 1;                                              \
            if (k < (C)) {                                                    \
                if (k >= 2) mbar_wait(EMPTYB(k & 1), (uint32_t)(((k >> 1) - 1) & 1)); \
                issue_chunk(k, k & 1);                                        \
            }                                                                 \
            mbar_wait(FULLB(c & 1), (uint32_t)((c >> 1) & 1));                \
            cchunk_i8(sb + (uint32_t)(c & 1) * STAGE, lane, mbase, nbase,     \
                      EMPTYB(c & 1), accH, accX);                             \
        }                                                                     \
    } while (0)

// ---------------------------------------------------------------- proj GEMM
// block: 128 tokens x 64 h; K=1536; direct fragment->global epilogue (R16 win)
__global__ __launch_bounds__(256, 2) void proj_i8(const float* __restrict__ lb,
                                                  const float* __restrict__ rb) {
    extern __shared__ char smem[];
    uint32_t sb = s2u(smem);
    const int tid = threadIdx.x, lane = tid & 31, wid = tid >> 5;
    const int mbase = (wid & 3) * 32, nbase = (wid >> 2) * 32;
    const int side = blockIdx.z, h0 = blockIdx.y * 64, token0 = blockIdx.x * 128;
    const int b = token0 >> 9, t0 = token0 & 511;

    const size_t abase = (size_t)(b * CSP + t0 + side * 2) * CD;
    const size_t wbase = (size_t)(side * 512 + h0) * CIN;

    if (tid == 0) {
        #pragma unroll
        for (int s = 0; s < NSTG; ++s) {
            mbar_init(FULLB(s), 256);
            mbar_init(EMPTYB(s), 8);
        }
    }
    __syncthreads();

    int accH[2][4][4] = {}, accX[2][4][4] = {};

    auto issue_chunk = [&](int c, int s) {
        uint32_t base = sb + (uint32_t)s * STAGE;
        int kb = c * 128;
        #pragma unroll
        for (int t = 0; t < 4; ++t) {
            int ci = tid + t * 256;
            uint32_t row = (uint32_t)(ci >> 3), slot = (uint32_t)(ci & 7);
            uint32_t so = soff(row, slot);
            size_t ga = abase + (size_t)row * CD + kb + slot * 16;
            cpa16(base + so,          g_aH + ga);
            cpa16(base + A_TERM + so, g_aL + ga);
        }
        #pragma unroll
        for (int t = 0; t < 2; ++t) {
            int ci = tid + t * 256;
            uint32_t row = (uint32_t)(ci >> 3), slot = (uint32_t)(ci & 7);
            uint32_t so = soff(row, slot);
            size_t gw = wbase + (size_t)row * CIN + kb + slot * 16;
            cpa16(base + 2 * A_TERM + so,          g_wpH + gw);
            cpa16(base + 2 * A_TERM + B_TERM + so, g_wpL + gw);
        }
        cpasync_arrive(FULLB(s));
    };

    GEMM_LOOP(CIN / 128);   // 12 chunks

    // direct epilogue: dequant + bias + relu, float2 stores (32B aligned)
    const float* bias = side ? rb : lb;
    const float sA = g_amaxv[0] * (1.f / QF);
    float tmax = 0.f;
    #pragma unroll
    for (int i = 0; i < 2; ++i)
        #pragma unroll
        for (int j = 0; j < 4; ++j) {
            int r = mbase + i * 16 + (lane >> 2);
            int c = nbase + j * 8 + (lane & 3) * 2;
            float s0 = sA * g_swp[side * 512 + h0 + c];
            float s1 = sA * g_swp[side * 512 + h0 + c + 1];
            #pragma unroll
            for (int half = 0; half < 2; ++half) {
                int rr = r + half * 8;
                float v0 = fmaxf(s0 * ((float)accH[i][j][half*2]   * 16384.f +
                                       (float)accX[i][j][half*2]   * 128.f) + bias[h0 + c], 0.f);
                float v1 = fmaxf(s1 * ((float)accH[i][j][half*2+1] * 16384.f +
                                       (float)accX[i][j][half*2+1] * 128.f) + bias[h0 + c + 1], 0.f);
                tmax = fmaxf(tmax, fmaxf(v0, v1));
                *(float2*)(g_f0 + ((size_t)side * CM + token0 + rr) * CD + h0 + c) =
                    make_float2(v0, v1);
            }
        }
    tmax = warp_max(tmax);
    if (lane == 0) amax_atomic(tmax, 1);
}

// ---------------------------------------------------------------- highway GEMM
// block: 128 tokens x 64 B-rows (32 nonlin, 32 gate); R15 all-warps epilogue
__global__ __launch_bounds__(256, 2) void hw_i8(const float* __restrict__ fin,
                                                float* __restrict__ fout,
                                                const float* __restrict__ lhwb,
                                                const float* __restrict__ rhwb,
                                                int layer, int aidx,
                                                float* __restrict__ out, int dup) {
    extern __shared__ char smem[];
    uint32_t sb = s2u(smem);
    const int tid = threadIdx.x, lane = tid & 31, wid = tid >> 5;
    const int mbase = (wid & 3) * 32, nbase = (wid >> 2) * 32;
    const int side = blockIdx.z, h0 = blockIdx.y * 32, token0 = blockIdx.x * 128;

    const size_t abase = ((size_t)side * CM + token0) * CD;
    const size_t wrow0 = (size_t)((side * 2 + layer) * 1024);

    if (tid == 0) {
        #pragma unroll
        for (int s = 0; s < NSTG; ++s) {
            mbar_init(FULLB(s), 256);
            mbar_init(EMPTYB(s), 8);
        }
    }
    __syncthreads();

    int accH[2][4][4] = {}, accX[2][4][4] = {};

    auto issue_chunk = [&](int c, int s) {
        uint32_t base = sb + (uint32_t)s * STAGE;
        int kb = c * 128;
        #pragma unroll
        for (int t = 0; t < 4; ++t) {
            int ci = tid + t * 256;
            uint32_t row = (uint32_t)(ci >> 3), slot = (uint32_t)(ci & 7);
            uint32_t so = soff(row, slot);
            size_t ga = abase + (size_t)row * CD + kb + slot * 16;
            cpa16(base + so,          g_xH + ga);
            cpa16(base + A_TERM + so, g_xL + ga);
        }
        #pragma unroll
        for (int t = 0; t < 2; ++t) {
            int ci = tid + t * 256;
            uint32_t row = (uint32_t)(ci >> 3), slot = (uint32_t)(ci & 7);
            int e = (row < 32) ? (h0 + (int)row) : (512 + h0 + (int)row - 32);
            uint32_t so = soff(row, slot);
            size_t gw = (wrow0 + e) * CD + kb + slot * 16;
            cpa16(base + 2 * A_TERM + so,          g_whH + gw);
            cpa16(base + 2 * A_TERM + B_TERM + so, g_whL + gw);
        }
        cpasync_arrive(FULLB(s));
    };

    GEMM_LOOP(CD / 128);    // 4 chunks
    __syncthreads();

    int* svH = (int*)smem;
    int* svX = svH + 128 * 68;
    acc2smem_i8(svH, svX, lane, mbase, nbase, accH, accX);
    __syncthreads();

    const float* bias = (side ? rhwb : lhwb) + (size_t)layer * 1024;
    const float sA = g_amaxv[aidx] * (1.f / QF);
    int row = tid >> 1, half = tid & 1;
    int token = token0 + row;
    float tmax = 0.f;
    #pragma unroll
    for (int c4 = 0; c4 < 4; ++c4) {
        int c0 = half * 16 + c4 * 4;                  // nonlin local col
        float4 xv = *(const float4*)(fin + ((size_t)side * CM + token) * CD + h0 + c0);
        const float* xp = &xv.x;
        float4 o;
        float* ov = &o.x;
        #pragma unroll
        for (int i = 0; i < 4; ++i) {
            int h = h0 + c0 + i;
            float dN = sA * g_swh[wrow0 + h] *
                       ((float)svH[row * 68 + c0 + i] * 16384.f +
                        (float)svX[row * 68 + c0 + i] * 128.f);
            float dG = sA * g_swh[wrow0 + 512 + h] *
                       ((float)svH[row * 68 + 32 + c0 + i] * 16384.f +
                        (float)svX[row * 68 + 32 + c0 + i] * 128.f);
            float nl = fmaxf(dN + bias[h], 0.f);
            float g  = 1.f / (1.f + expf(-(dG + bias[512 + h])));
            ov[i] = g * xp[i] + (1.f - g) * nl;
            tmax = fmaxf(tmax, fabsf(ov[i]));
        }
        if (out) {
            size_t oo = (size_t)token * 1024 + (size_t)side * 512 + h0 + c0;
            *(float4*)(out + oo) = o;
            if (dup) *(float4*)(out + NOUT + oo) = o;
        } else {
            *(float4*)(fout + ((size_t)side * CM + token) * CD + h0 + c0) = o;
        }
    }
    if (!out) {
        tmax = warp_max(tmax);
        if (lane == 0) amax_atomic(tmax, aidx + 1);
    }
}

// ---------------------------------------------------------------- launcher
extern "C" void kernel_launch(void* const* d_in, const int* in_sizes, int n_in,
                              void* d_out, int out_size) {
    const float* inputs = (const float*)d_in[0];
    const float* lpad   = (const float*)d_in[1];
    const float* rpad   = (const float*)d_in[2];
    const float* lW     = (const float*)d_in[3];
    const float* lb     = (const float*)d_in[4];
    const float* rW     = (const float*)d_in[5];
    const float* rb     = (const float*)d_in[6];
    const float* lhwW   = (const float*)d_in[7];
    const float* lhwb   = (const float*)d_in[8];
    const float* rhwW   = (const float*)d_in[9];
    const float* rhwb   = (const float*)d_in[10];
    float* out = (float*)d_out;
    int dup = (out_size >= 2 * NOUT) ? 1 : 0;

    cudaFuncSetAttribute(proj_i8, cudaFuncAttributeMaxDynamicSharedMemorySize, SMEM_SZ);
    cudaFuncSetAttribute(hw_i8,   cudaFuncAttributeMaxDynamicSharedMemorySize, SMEM_SZ);

    float *f0, *f1;
    cudaGetSymbolAddress((void**)&f0, g_f0);
    cudaGetSymbolAddress((void**)&f1, g_f1);

    zero_amax<<<1, 32>>>();
    amax_in<<<(CB * CS * CD / 4 + 512 + 255) / 256, 256>>>(inputs, lpad, rpad);
    prep_quant<<<PADQ_BLKS + 5120, 128>>>(inputs, lpad, rpad, lW, rW, lhwW, rhwW);
    proj_i8<<<dim3(CM / 128, 8, 2), 256, SMEM_SZ>>>(lb, rb);
    quant_act<<<(2 * CM * CD / 4 + 255) / 256, 256>>>(f0, 1);
    hw_i8<<<dim3(CM / 128, 16, 2), 256, SMEM_SZ>>>(f0, f1, lhwb, rhwb, 0, 1, nullptr, 0);
    quant_act<<<(2 * CM * CD / 4 + 255) / 256, 256>>>(f1, 2);
    hw_i8<<<dim3(CM / 128, 16, 2), 256, SMEM_SZ>>>(f1, nullptr, lhwb, rhwb, 1, 2, out, dup);
}